// round 17
// baseline (speedup 1.0000x reference)
#include <cuda_runtime.h>

// ---------------------------------------------------------------------------
// ContrastiveCRFLoss — B200 (sm_100a), round 17: SINGLE kernel.
//
// Phases by block id (one launch; cross-phase ordering via flag/counters):
//   bid 0                : spatial counting sort -> fence -> d_flag
//   bid 1..4096          : zero-fill 128MB output (sort hides under wave 1)
//   bid .. +3375         : sorted gather (spins on d_flag; safety-only),
//                          then fence + d_gdone++
//   bid .. +4096         : pair enumeration b>=a (symmetry), then d_pdone++
//   bid .. +448 (last)   : SPARSE phase — spins until d_gdone==GB &&
//                          d_pdone==PB (producers all have lower bids, so
//                          they are dispatched/retired first; spin bounded),
//                          then warp-per-pair compute, writes both symmetric
//                          cells; last sparse block resets all counters.
//
// Exact-zero sparsity: out[n,a,b] != -0.0 only for integer pixel-dist^2
// cd <= 105; out is symmetric in (a,b) exactly (verified vs reference).
// ---------------------------------------------------------------------------

#define NB    32
#define KC    27
#define NS    1000
#define HW    256
#define MAXP  32768
#define CD_MAX 105.0f

#define ZB    4096
#define GB    3375
#define PB    4096
#define SPB   448
#define NBLK  (1 + ZB + GB + PB + SPB)     // 12016

__device__ float    d_recT[NS * 32 * NB];     // 4 MB  [s][word][n]
__device__ int      d_order[1024];
__device__ unsigned d_pairs[MAXP];            // (a<<10)|b,  b >= a
__device__ float    d_pcd[MAXP];
__device__ int      d_npairs;                 // static 0; reset by sparse tail
__device__ int      d_flag;                   // sort done
__device__ int      d_gdone;                  // gather blocks done
__device__ int      d_pdone;                  // pair blocks done
__device__ int      d_sdone;                  // sparse blocks done

// ---------------------------------------------------------------------------
__global__ void __launch_bounds__(256)
mega_k(const float* __restrict__ guidance,
       const float* __restrict__ clusters,
       const int*   __restrict__ coords,
       float4* __restrict__ out, int n4) {
    const int bid = blockIdx.x;
    const int tid = threadIdx.x;

    if (bid == 0) {
        // ---- counting sort by spatial bin (px >> 6) — R10-validated ----
        __shared__ int hist[1024];
        __shared__ int base[1024];
        __shared__ int wsum[8];
        __shared__ short sbin[NS];
        __shared__ short srank[NS];

        #pragma unroll
        for (int q = 0; q < 4; q++) hist[q * 256 + tid] = 0;
        __syncthreads();

        #pragma unroll
        for (int q = 0; q < 4; q++) {
            int i = q * 256 + tid;
            if (i < NS) {
                int r = __ldg(&coords[i]);
                int c = __ldg(&coords[NS + i]);
                int bin = (r * 256 + c) >> 6;
                sbin[i]  = (short)bin;
                srank[i] = (short)atomicAdd(&hist[bin], 1);
            }
        }
        __syncthreads();

        int h0 = hist[4 * tid + 0], h1 = hist[4 * tid + 1];
        int h2 = hist[4 * tid + 2], h3 = hist[4 * tid + 3];
        int tsum = h0 + h1 + h2 + h3;

        const int lane = tid & 31, w = tid >> 5;
        int v = tsum;
        #pragma unroll
        for (int o = 1; o < 32; o <<= 1) {
            int t = __shfl_up_sync(0xffffffffu, v, o);
            if (lane >= o) v += t;
        }
        if (lane == 31) wsum[w] = v;
        __syncthreads();
        if (tid < 8) {
            int s = wsum[tid];
            #pragma unroll
            for (int o = 1; o < 8; o <<= 1) {
                int t = __shfl_up_sync(0xffu, s, o);
                if (tid >= o) s += t;
            }
            wsum[tid] = s;
        }
        __syncthreads();
        int excl = ((w == 0) ? 0 : wsum[w - 1]) + v - tsum;
        base[4 * tid + 0] = excl;
        base[4 * tid + 1] = excl + h0;
        base[4 * tid + 2] = excl + h0 + h1;
        base[4 * tid + 3] = excl + h0 + h1 + h2;
        __syncthreads();

        #pragma unroll
        for (int q = 0; q < 4; q++) {
            int i = q * 256 + tid;
            if (i < NS)
                d_order[base[sbin[i]] + srank[i]] = i;
        }
        __syncthreads();
        if (tid == 0) {
            __threadfence();
            atomicExch(&d_flag, 1);
        }
    } else if (bid <= ZB) {
        // ---- zero-fill output ----
        int zidx = (bid - 1) * 256 + tid;
        float4 z = make_float4(0.f, 0.f, 0.f, 0.f);
        #pragma unroll
        for (int it = 0; it < 8; it++) {
            int i = zidx + it * (ZB * 256);
            if (i < n4) out[i] = z;
        }
    } else if (bid <= ZB + GB) {
        // ---- sorted gather ----
        if (tid == 0) {
            while (atomicAdd(&d_flag, 0) == 0) { __nanosleep(64); }
        }
        __syncthreads();

        int idx = (bid - ZB - 1) * 256 + tid;          // < 864000 exactly
        int nk   = idx / NS;
        int sIdx = idx - nk * NS;
        int n = nk / KC;
        int k = nk - n * KC;

        int s = __ldcg(&d_order[sIdx]);
        int r = __ldg(&coords[s]);
        int c = __ldg(&coords[NS + s]);
        int px = r * HW + c;

        float v = clusters[((size_t)nk * HW * HW) + px];
        d_recT[((size_t)s * 32 + k) * NB + n] = v;

        if (k < 3) {
            float g = guidance[(((size_t)n * 3 + k) * HW * HW) + px];
            d_recT[((size_t)s * 32 + 27 + k) * NB + n] = g;
        }

        __syncthreads();
        if (tid == 0) {
            __threadfence();                       // recT stores visible
            atomicAdd(&d_gdone, 1);
        }
    } else if (bid <= ZB + GB + PB) {
        // ---- pair enumeration, b >= a only ----
        int idx = (bid - 1 - ZB - GB) * 256 + tid;
        int a = idx >> 10;
        int b = idx & 1023;
        if (a < NS && b < NS && b >= a) {
            float dr = (float)(__ldg(&coords[a])      - __ldg(&coords[b]));
            float dc = (float)(__ldg(&coords[NS + a]) - __ldg(&coords[NS + b]));
            float cd = dr * dr + dc * dc;
            if (cd <= CD_MAX) {
                int pos = atomicAdd(&d_npairs, 1);
                if (pos < MAXP) {
                    d_pairs[pos] = ((unsigned)a << 10) | (unsigned)b;
                    d_pcd[pos]   = cd;
                }
            }
        }
        __syncthreads();
        if (tid == 0) {
            __threadfence();                       // pair list visible
            atomicAdd(&d_pdone, 1);
        }
    } else {
        // ---- SPARSE phase: wait for gather + pairs, then compute ----
        if (tid == 0) {
            while (atomicAdd(&d_gdone, 0) < GB ||
                   atomicAdd(&d_pdone, 0) < PB) { __nanosleep(128); }
        }
        __syncthreads();
        __threadfence();                           // acquire

        const int lane = tid & 31;
        int np = atomicAdd(&d_npairs, 0);
        if (np > MAXP) np = MAXP;

        const int W = (SPB * 256) >> 5;            // 3584 warps
        int sbid = bid - 1 - ZB - GB - PB;         // [0, SPB)
        float* outf = (float*)out;

        for (int gw = (sbid * 256 + tid) >> 5; gw < np; gw += W) {
            unsigned pr = d_pairs[gw];
            int a = (int)(pr >> 10);
            int b = (int)(pr & 1023u);
            float cd = d_pcd[gw];

            const float* ra = d_recT + (size_t)a * 32 * NB + lane;
            const float* rb = d_recT + (size_t)b * 32 * NB + lane;

            float dot = 0.f;
            #pragma unroll
            for (int k = 0; k < KC; k++)
                dot = fmaf(__ldcg(ra + k * NB), __ldcg(rb + k * NB), dot);

            float gd = 0.f;
            #pragma unroll
            for (int ch = 0; ch < 3; ch++) {
                float d = __ldcg(ra + (27 + ch) * NB) - __ldcg(rb + (27 + ch) * NB);
                gd = fmaf(d, d, gd);
            }

            float s1 = 10.0f * __expf(-cd - gd * 3.33333333f);
            float s2 = 3.0f  * __expf(-10.0f * cd);
            float val = -dot * (s1 + s2);

            size_t planeBase = (size_t)lane * NS * NS;
            outf[planeBase + (size_t)a * NS + b] = val;
            if (b != a)
                outf[planeBase + (size_t)b * NS + a] = val;
        }

        // ---- last sparse block resets all cross-call state.
        // Every counter/np read above precedes this block's barrier; reset
        // fires only after ALL sparse blocks arrive (R10-validated pattern).
        __syncthreads();
        if (tid == 0) {
            int t = atomicAdd(&d_sdone, 1);
            if (t == SPB - 1) {
                d_npairs = 0;
                d_flag   = 0;
                d_gdone  = 0;
                d_pdone  = 0;
                d_sdone  = 0;
            }
        }
    }
}

// ---------------------------------------------------------------------------
extern "C" void kernel_launch(void* const* d_in, const int* in_sizes, int n_in,
                              void* d_out, int out_size) {
    const float* guidance = (const float*)d_in[0];
    const float* clusters = (const float*)d_in[1];
    const int*   coords   = (const int*)d_in[2];
    float* out = (float*)d_out;

    mega_k<<<NBLK, 256>>>(guidance, clusters, coords,
                          (float4*)out, out_size / 4);
}